// round 6
// baseline (speedup 1.0000x reference)
#include <cuda_runtime.h>
#include <cstdint>

// PSRoIPool, plane-staged: x (4, 1029, 96, 96) fp32, rois (512,5) fp32.
// out (512, 21, 7, 7): out[k*1029 + p] pools plane p = c*49+i*7+j of batch b_k
// over bin (i,j) of roi k.  Block per plane p; for each batch b, stage the
// 36 KB plane in smem (coalesced float4), then threads compute all rois with
// that b from smem.
//
// NUMERIC CONTRACT (verified R5): bin sizes are reciprocal-multiplies
// (__fmul_rn with fl(1/7)), NOT divisions. Do not change.

#define C_TOT   1029
#define PH      7
#define PW      7
#define HH      96
#define WW      96
#define PLANE   (HH*WW)       // 9216 floats
#define KROIS   512
#define NBATCH  4
#define SCALE   0.0625f
#define RCP7    0.1428571492433547973632812500f   // fl(1/7) = 0x3E124925
#define THREADS 256

__global__ __launch_bounds__(THREADS) void psroi_plane(
    const float* __restrict__ x,
    const float* __restrict__ rois,
    float* __restrict__ out)
{
    __shared__ float sp[PLANE];            // 36864 B
    const int p   = blockIdx.x;            // channel/plane 0..1028
    const int ij  = p % (PH * PW);
    const int i   = ij / PW;
    const int j   = ij - i * PW;
    const int tid = threadIdx.x;

    // Decode this thread's two rois once (k = tid, tid+256).
    int rb[2], rhs[2], rhe[2], rws[2], rwe[2];
    #pragma unroll
    for (int t = 0; t < 2; ++t) {
        const int k = tid + t * THREADS;
        const float* roi = rois + k * 5;
        int b  = (int)roi[0];
        int sw = (int)floorf(__fmaf_rn(roi[1], SCALE, 0.5f));
        int sh = (int)floorf(__fmaf_rn(roi[2], SCALE, 0.5f));
        int ew = (int)floorf(__fmaf_rn(roi[3], SCALE, 0.5f));
        int eh = (int)floorf(__fmaf_rn(roi[4], SCALE, 0.5f));
        float bin_h = __fmul_rn((float)max(eh - sh, 1), RCP7);
        float bin_w = __fmul_rn((float)max(ew - sw, 1), RCP7);
        rb[t]  = b;
        rhs[t] = min(max((int)floorf(__fmul_rn((float)i,       bin_h)) + sh, 0), HH);
        rhe[t] = min(max((int)ceilf (__fmul_rn((float)(i + 1), bin_h)) + sh, 0), HH);
        rws[t] = min(max((int)floorf(__fmul_rn((float)j,       bin_w)) + sw, 0), WW);
        rwe[t] = min(max((int)ceilf (__fmul_rn((float)(j + 1), bin_w)) + sw, 0), WW);
    }

    for (int b = 0; b < NBATCH; ++b) {
        __syncthreads();   // previous pass's readers done before overwrite
        // Stage plane (b, p): 2304 float4, 9 per thread, fully coalesced.
        const float4* __restrict__ src =
            (const float4*)(x + ((size_t)b * C_TOT + p) * PLANE);
        float4* dst = (float4*)sp;
        #pragma unroll
        for (int q = 0; q < PLANE / 4 / THREADS; ++q)   // 9
            dst[tid + q * THREADS] = src[tid + q * THREADS];
        __syncthreads();

        #pragma unroll
        for (int t = 0; t < 2; ++t) {
            if (rb[t] != b) continue;
            const int k = tid + t * THREADS;
            int area = (rhe[t] - rhs[t]) * (rwe[t] - rws[t]);
            float val = 0.0f;
            if (area > 0) {
                float s = 0.0f;
                for (int hy = rhs[t]; hy < rhe[t]; ++hy) {
                    const float* row = sp + hy * WW;
                    for (int wx = rws[t]; wx < rwe[t]; ++wx)
                        s += row[wx];
                }
                val = __fdiv_rn(s, (float)area);
            }
            out[k * C_TOT + p] = val;   // every output written in its b-pass
        }
    }
}

extern "C" void kernel_launch(void* const* d_in, const int* in_sizes, int n_in,
                              void* d_out, int out_size)
{
    const float* x;
    const float* rois;
    if (n_in >= 2 && in_sizes[0] == KROIS * 5) {
        rois = (const float*)d_in[0];
        x    = (const float*)d_in[1];
    } else {
        x    = (const float*)d_in[0];
        rois = (const float*)d_in[1];
    }
    float* out = (float*)d_out;

    psroi_plane<<<C_TOT, THREADS>>>(x, rois, out);
}